// round 2
// baseline (speedup 1.0000x reference)
#include <cuda_runtime.h>
#include <math.h>

#define BB 256
#define SS 512
#define II 256
#define HH 256
#define OO 256
#define LL 64

// Scratch: xproj[s][b][h] = x[b,s,:]@W1x + b1x + b1a   (134 MB, static device array)
__device__ float g_xproj[(size_t)SS * BB * HH];

__device__ __forceinline__ float sigf(float x) {
    return 1.f / (1.f + expf(-x));
}
// tanh via exp: robust for all x (inf handled), ~1e-7 rel err, flag-independent
__device__ __forceinline__ float tanhfast(float x) {
    float e = expf(2.f * x);
    return 1.f - 2.f / (e + 1.f);
}

// ---------------------------------------------------------------------------
// Kernel 1: xproj = x @ W1x + (b1x + b1a), written as [s][b][h]
// Each CTA: 16 consecutive (s,b) rows (same s), 256 threads = 256 output cols.
// W1x streamed from L2 (coalesced, shared across CTAs); x rows staged in SMEM
// packed per-k across the 16 rows so reads are float4 broadcasts.
// ---------------------------------------------------------------------------
__global__ __launch_bounds__(256, 2) void xproj_kernel(
    const float* __restrict__ x, const float* __restrict__ W1x,
    const float* __restrict__ b1x, const float* __restrict__ b1a)
{
    __shared__ float xs[II * 16];          // [k][r], r-stride 1, k-stride 16
    const int t  = threadIdx.x;            // load phase: t = k ; compute: t = h
    const int m0 = blockIdx.x * 16;        // m = s*256 + b
    const int s  = m0 >> 8;
    const int b0 = m0 & 255;

    #pragma unroll
    for (int r = 0; r < 16; r++)
        xs[t * 16 + r] = x[(size_t)(b0 + r) * (SS * II) + (size_t)s * II + t];
    __syncthreads();

    float acc[16];
    #pragma unroll
    for (int r = 0; r < 16; r++) acc[r] = 0.f;

    const float* Wp = W1x + t;              // W1x[k][h], column h = t
    #pragma unroll 4
    for (int k = 0; k < II; k++) {
        float w = Wp[(size_t)k * HH];
        const float4* xk = (const float4*)(xs + k * 16);
        #pragma unroll
        for (int q = 0; q < 4; q++) {
            float4 v = xk[q];
            acc[q * 4 + 0] = fmaf(v.x, w, acc[q * 4 + 0]);
            acc[q * 4 + 1] = fmaf(v.y, w, acc[q * 4 + 1]);
            acc[q * 4 + 2] = fmaf(v.z, w, acc[q * 4 + 2]);
            acc[q * 4 + 3] = fmaf(v.w, w, acc[q * 4 + 3]);
        }
    }

    float bias = b1x[t] + b1a[t];
    #pragma unroll
    for (int r = 0; r < 16; r++)
        g_xproj[(size_t)(m0 + r) * HH + t] = acc[r] + bias;
}

// ---------------------------------------------------------------------------
// GEMV helper: for this thread's output column (W column pointer Wcol, row
// stride = 256), accumulate over K shared float4 entries (4 batch rows packed).
// Weight loads are fully coalesced across the warp (consecutive h), shared
// reads are single-address float4 broadcasts. #pragma unroll 8 gives MLP~8.
// ---------------------------------------------------------------------------
__device__ __forceinline__ float4 gemv4(const float* __restrict__ Wcol,
                                        const float4* avec, int K) {
    float4 acc = make_float4(0.f, 0.f, 0.f, 0.f);
    #pragma unroll 8
    for (int k = 0; k < K; k++) {
        float  w = Wcol[(size_t)k * 256];
        float4 v = avec[k];
        acc.x = fmaf(v.x, w, acc.x);
        acc.y = fmaf(v.y, w, acc.y);
        acc.z = fmaf(v.z, w, acc.z);
        acc.w = fmaf(v.w, w, acc.w);
    }
    return acc;
}

// ---------------------------------------------------------------------------
// Kernel 2: persistent RNN. Grid = 64 CTAs, each owns 4 independent batch
// rows for the entire encoder+decoder. Hidden state lives in SMEM packed
// float4 (4 rows per k). Weights stream from L2 every step (L2-resident).
// No inter-CTA communication needed (batch rows are independent).
// ---------------------------------------------------------------------------
__global__ __launch_bounds__(256, 1) void rnn_kernel(
    const float* __restrict__ W1a,
    const float* __restrict__ W2x, const float* __restrict__ b2x,
    const float* __restrict__ W2a, const float* __restrict__ b2a,
    const float* __restrict__ Wy,  const float* __restrict__ by,
    float* __restrict__ out)
{
    __shared__ float4 a4[HH];   // a[k] for this CTA's 4 batch rows
    __shared__ float4 y4[OO];   // y0 staging

    const int h  = threadIdx.x;
    const int b0 = blockIdx.x * 4;

    a4[h] = make_float4(0.f, 0.f, 0.f, 0.f);
    __syncthreads();

    // ---------------- encoder: a = tanh(xproj_s + a @ W1a) ----------------
    for (int s = 0; s < SS; s++) {
        const float* xp = &g_xproj[((size_t)s * BB + b0) * HH + h];
        float xp0 = xp[0];
        float xp1 = xp[HH];
        float xp2 = xp[2 * HH];
        float xp3 = xp[3 * HH];

        float4 acc = gemv4(W1a + h, a4, HH);

        __syncthreads();                    // all reads of a4 done
        a4[h] = make_float4(tanhfast(xp0 + acc.x), tanhfast(xp1 + acc.y),
                            tanhfast(xp2 + acc.z), tanhfast(xp3 + acc.w));
        __syncthreads();                    // new a4 visible
    }

    // ---------------- y0 = sigmoid(a_last @ Wy + by) ----------------
    {
        float4 acc = gemv4(Wy + h, a4, HH);
        float bv = by[h];
        y4[h] = make_float4(sigf(acc.x + bv), sigf(acc.y + bv),
                            sigf(acc.z + bv), sigf(acc.w + bv));
        __syncthreads();
    }

    // ---------------- base0 = y0 @ W2x + b2x + b2a ; bbias for i>0 --------
    const float bbv = b2x[h] + b2a[h];
    float4 base0 = gemv4(W2x + h, y4, OO);
    base0.x += bbv; base0.y += bbv; base0.z += bbv; base0.w += bbv;

    // ---------------- decoder ----------------
    for (int i = 0; i < LL; i++) {
        float4 base = (i == 0) ? base0 : make_float4(bbv, bbv, bbv, bbv);

        float4 acc = gemv4(W2a + h, a4, HH);
        __syncthreads();
        a4[h] = make_float4(tanhfast(base.x + acc.x), tanhfast(base.y + acc.y),
                            tanhfast(base.z + acc.z), tanhfast(base.w + acc.w));
        __syncthreads();

        // y_i = sigmoid(a_new @ Wy + by)  (thread h = output column o)
        float4 yacc = gemv4(Wy + h, a4, HH);
        float bv = by[h];
        out[((size_t)(b0 + 0) * LL + i) * OO + h] = sigf(yacc.x + bv);
        out[((size_t)(b0 + 1) * LL + i) * OO + h] = sigf(yacc.y + bv);
        out[((size_t)(b0 + 2) * LL + i) * OO + h] = sigf(yacc.z + bv);
        out[((size_t)(b0 + 3) * LL + i) * OO + h] = sigf(yacc.w + bv);
        // no trailing sync needed: next write to a4 is guarded by the sync
        // after the next iteration's gemv (which also reads a4)
    }
}

// ---------------------------------------------------------------------------
extern "C" void kernel_launch(void* const* d_in, const int* in_sizes, int n_in,
                              void* d_out, int out_size)
{
    const float* x   = (const float*)d_in[0];
    const float* W1x = (const float*)d_in[1];
    const float* b1x = (const float*)d_in[2];
    const float* W1a = (const float*)d_in[3];
    const float* b1a = (const float*)d_in[4];
    const float* W2x = (const float*)d_in[5];
    const float* b2x = (const float*)d_in[6];
    const float* W2a = (const float*)d_in[7];
    const float* b2a = (const float*)d_in[8];
    const float* Wy  = (const float*)d_in[9];
    const float* by  = (const float*)d_in[10];
    float* out = (float*)d_out;

    (void)in_sizes; (void)n_in; (void)out_size;

    xproj_kernel<<<(BB * SS) / 16, 256>>>(x, W1x, b1x, b1a);
    rnn_kernel<<<BB / 4, 256>>>(W1a, W2x, b2x, W2a, b2a, Wy, by, out);
}

// round 3
// speedup vs baseline: 1.9040x; 1.9040x over previous
#include <cuda_runtime.h>
#include <math.h>

#define BB 256
#define SS 512
#define II 256
#define HH 256
#define OO 256
#define LL 64

// Scratch: xproj[s][b][h] = x[b,s,:]@W1x + b1x + b1a   (134 MB)
__device__ float g_xproj[(size_t)SS * BB * HH];

__device__ __forceinline__ float sigf(float x) {
    return 1.f / (1.f + expf(-x));
}
__device__ __forceinline__ float tanhfast(float x) {
    float e = expf(2.f * x);
    return 1.f - 2.f / (e + 1.f);
}

// ---------------------------------------------------------------------------
// Kernel 1: xproj = x @ W1x + (b1x+b1a), tiled SGEMM.
// CTA tile M=64 (rows m = s*256+b), N=64, K-step 16, double-buffered SMEM.
// 256 threads, 4x4 microtile each. As stored K-major transposed: As[k][m].
// ---------------------------------------------------------------------------
__global__ __launch_bounds__(256) void xproj_kernel(
    const float* __restrict__ x, const float* __restrict__ W1x,
    const float* __restrict__ b1x, const float* __restrict__ b1a)
{
    __shared__ float As[2][16][64];
    __shared__ float Bs[2][16][64];

    const int t  = threadIdx.x;
    const int tx = t & 15;          // col quad
    const int ty = t >> 4;          // row quad
    const int m0 = blockIdx.x * 64; // m = s*256 + b
    const int n0 = blockIdx.y * 64;
    const int s  = m0 >> 8;
    const int b0 = m0 & 255;

    // loader roles
    const int ar = t >> 2;          // A row 0..63
    const int ak = t & 3;           // A k-quad 0..3
    const int bk = t >> 4;          // B k-row 0..15
    const int bn = t & 15;          // B col-quad 0..15

    const float* aptr = x + ((size_t)(b0 + ar) * SS + s) * II + ak * 4;
    const float* bptr = W1x + (size_t)bk * HH + n0 + bn * 4;

    float4 areg = *(const float4*)aptr;
    float4 breg = *(const float4*)bptr;
    As[0][ak * 4 + 0][ar] = areg.x;
    As[0][ak * 4 + 1][ar] = areg.y;
    As[0][ak * 4 + 2][ar] = areg.z;
    As[0][ak * 4 + 3][ar] = areg.w;
    *(float4*)&Bs[0][bk][bn * 4] = breg;
    __syncthreads();

    float4 acc[4];
    #pragma unroll
    for (int r = 0; r < 4; r++) acc[r] = make_float4(0.f, 0.f, 0.f, 0.f);

    #pragma unroll 1
    for (int step = 0; step < 16; step++) {
        const int p = step & 1;
        if (step < 15) {
            areg = *(const float4*)(aptr + (step + 1) * 16);
            breg = *(const float4*)(bptr + (size_t)(step + 1) * 16 * HH);
        }
        #pragma unroll
        for (int k = 0; k < 16; k++) {
            float4 av = *(const float4*)&As[p][k][ty * 4];
            float4 bv = *(const float4*)&Bs[p][k][tx * 4];
            acc[0].x = fmaf(av.x, bv.x, acc[0].x); acc[0].y = fmaf(av.x, bv.y, acc[0].y);
            acc[0].z = fmaf(av.x, bv.z, acc[0].z); acc[0].w = fmaf(av.x, bv.w, acc[0].w);
            acc[1].x = fmaf(av.y, bv.x, acc[1].x); acc[1].y = fmaf(av.y, bv.y, acc[1].y);
            acc[1].z = fmaf(av.y, bv.z, acc[1].z); acc[1].w = fmaf(av.y, bv.w, acc[1].w);
            acc[2].x = fmaf(av.z, bv.x, acc[2].x); acc[2].y = fmaf(av.z, bv.y, acc[2].y);
            acc[2].z = fmaf(av.z, bv.z, acc[2].z); acc[2].w = fmaf(av.z, bv.w, acc[2].w);
            acc[3].x = fmaf(av.w, bv.x, acc[3].x); acc[3].y = fmaf(av.w, bv.y, acc[3].y);
            acc[3].z = fmaf(av.w, bv.z, acc[3].z); acc[3].w = fmaf(av.w, bv.w, acc[3].w);
        }
        if (step < 15) {
            const int q = 1 - p;
            As[q][ak * 4 + 0][ar] = areg.x;
            As[q][ak * 4 + 1][ar] = areg.y;
            As[q][ak * 4 + 2][ar] = areg.z;
            As[q][ak * 4 + 3][ar] = areg.w;
            *(float4*)&Bs[q][bk][bn * 4] = breg;
            __syncthreads();
        }
    }

    float4 bx = *(const float4*)&b1x[n0 + tx * 4];
    float4 ba = *(const float4*)&b1a[n0 + tx * 4];
    float4 bias = make_float4(bx.x + ba.x, bx.y + ba.y, bx.z + ba.z, bx.w + ba.w);
    #pragma unroll
    for (int r = 0; r < 4; r++) {
        float4 v = make_float4(acc[r].x + bias.x, acc[r].y + bias.y,
                               acc[r].z + bias.z, acc[r].w + bias.w);
        *(float4*)&g_xproj[(size_t)(m0 + ty * 4 + r) * HH + n0 + tx * 4] = v;
    }
}

// ---------------------------------------------------------------------------
// Kernel 2: persistent RNN, 64 CTAs x 4 batch rows, K-split GEMV.
// Thread = (kg = t>>6, hq = t&63). GEMV partial: 64 k-iters of
// LDG.128 weights (4 cols) x SMEM float4 a (4 rows) = 16 FMA per load.
// Partials reduced through SMEM; thread t==h does activation + state write.
// ---------------------------------------------------------------------------
__shared__ float4 sh_a4[HH];          // a[k], float4 over 4 batch rows
__device__ __forceinline__ void gemv_part(const float* __restrict__ Wcol,
                                          const float4* __restrict__ a,
                                          int kbase, float4 acc[4])
{
    const float* Wp = Wcol + (size_t)kbase * 256;
    #pragma unroll 8
    for (int k = 0; k < 64; k++) {
        float4 w  = *(const float4*)(Wp + (size_t)k * 256);
        float4 av = a[kbase + k];
        acc[0].x = fmaf(av.x, w.x, acc[0].x); acc[0].y = fmaf(av.x, w.y, acc[0].y);
        acc[0].z = fmaf(av.x, w.z, acc[0].z); acc[0].w = fmaf(av.x, w.w, acc[0].w);
        acc[1].x = fmaf(av.y, w.x, acc[1].x); acc[1].y = fmaf(av.y, w.y, acc[1].y);
        acc[1].z = fmaf(av.y, w.z, acc[1].z); acc[1].w = fmaf(av.y, w.w, acc[1].w);
        acc[2].x = fmaf(av.z, w.x, acc[2].x); acc[2].y = fmaf(av.z, w.y, acc[2].y);
        acc[2].z = fmaf(av.z, w.z, acc[2].z); acc[2].w = fmaf(av.z, w.w, acc[2].w);
        acc[3].x = fmaf(av.w, w.x, acc[3].x); acc[3].y = fmaf(av.w, w.y, acc[3].y);
        acc[3].z = fmaf(av.w, w.z, acc[3].z); acc[3].w = fmaf(av.w, w.w, acc[3].w);
    }
}

__global__ __launch_bounds__(256, 1) void rnn_kernel(
    const float* __restrict__ W1a,
    const float* __restrict__ W2x, const float* __restrict__ b2x,
    const float* __restrict__ W2a, const float* __restrict__ b2a,
    const float* __restrict__ Wy,  const float* __restrict__ by,
    float* __restrict__ out)
{
    __shared__ float4 a4[HH];      // state: a[k] over 4 rows
    __shared__ float4 y4[OO];      // y0 staging
    __shared__ float4 red[4 * 64 * 4];   // [kg][hq][r] float4 over 4 cols
    __shared__ float4 red2[4 * 64 * 4];

    const int t   = threadIdx.x;
    const int kg  = t >> 6;
    const int hq  = t & 63;
    const int h4  = hq * 4;
    const int kbase = kg * 64;
    const int b0  = blockIdx.x * 4;
    const int rbase = (kg * 64 + hq) * 4;
    const float* redf  = (const float*)red;
    const float* red2f = (const float*)red2;
    const int rhq = t >> 2;        // reducer: hq of column t
    const int rc  = t & 3;         // reducer: component of column t

    a4[t] = make_float4(0.f, 0.f, 0.f, 0.f);
    __syncthreads();

    // ---------------- encoder ----------------
    for (int s = 0; s < SS; s++) {
        // prefetch xproj for reducer role (col t, rows 0..3); covered by gemv
        const float* xp = &g_xproj[((size_t)s * BB + b0) * HH + t];
        float xp0 = xp[0], xp1 = xp[HH], xp2 = xp[2 * HH], xp3 = xp[3 * HH];

        float4 acc[4];
        #pragma unroll
        for (int r = 0; r < 4; r++) acc[r] = make_float4(0.f, 0.f, 0.f, 0.f);
        gemv_part(W1a + h4, a4, kbase, acc);
        #pragma unroll
        for (int r = 0; r < 4; r++) red[rbase + r] = acc[r];
        __syncthreads();

        float v0 = 0.f, v1 = 0.f, v2 = 0.f, v3 = 0.f;
        #pragma unroll
        for (int g = 0; g < 4; g++) {
            int base = ((g * 64 + rhq) * 4) * 4 + rc;
            v0 += redf[base];
            v1 += redf[base + 4];
            v2 += redf[base + 8];
            v3 += redf[base + 12];
        }
        a4[t] = make_float4(tanhfast(xp0 + v0), tanhfast(xp1 + v1),
                            tanhfast(xp2 + v2), tanhfast(xp3 + v3));
        __syncthreads();
    }

    const float byv = by[t];
    const float bbv = b2x[t] + b2a[t];

    // ---------------- y0 = sigmoid(a @ Wy + by) ----------------
    {
        float4 acc[4];
        #pragma unroll
        for (int r = 0; r < 4; r++) acc[r] = make_float4(0.f, 0.f, 0.f, 0.f);
        gemv_part(Wy + h4, a4, kbase, acc);
        #pragma unroll
        for (int r = 0; r < 4; r++) red2[rbase + r] = acc[r];
        __syncthreads();
        float v0 = 0.f, v1 = 0.f, v2 = 0.f, v3 = 0.f;
        #pragma unroll
        for (int g = 0; g < 4; g++) {
            int base = ((g * 64 + rhq) * 4) * 4 + rc;
            v0 += red2f[base]; v1 += red2f[base + 4];
            v2 += red2f[base + 8]; v3 += red2f[base + 12];
        }
        y4[t] = make_float4(sigf(v0 + byv), sigf(v1 + byv),
                            sigf(v2 + byv), sigf(v3 + byv));
        __syncthreads();
    }

    // ---------------- base0 = y0 @ W2x + (b2x+b2a) ----------------
    float base0[4];
    {
        float4 acc[4];
        #pragma unroll
        for (int r = 0; r < 4; r++) acc[r] = make_float4(0.f, 0.f, 0.f, 0.f);
        gemv_part(W2x + h4, y4, kbase, acc);
        #pragma unroll
        for (int r = 0; r < 4; r++) red[rbase + r] = acc[r];
        __syncthreads();
        #pragma unroll
        for (int r = 0; r < 4; r++) {
            float v = 0.f;
            #pragma unroll
            for (int g = 0; g < 4; g++)
                v += redf[((g * 64 + rhq) * 4 + r) * 4 + rc];
            base0[r] = v + bbv;
        }
        __syncthreads();
    }

    // ---------------- decoder ----------------
    for (int i = 0; i < LL; i++) {
        // a = tanh(base + a @ W2a)
        {
            float4 acc[4];
            #pragma unroll
            for (int r = 0; r < 4; r++) acc[r] = make_float4(0.f, 0.f, 0.f, 0.f);
            gemv_part(W2a + h4, a4, kbase, acc);
            #pragma unroll
            for (int r = 0; r < 4; r++) red[rbase + r] = acc[r];
            __syncthreads();
            float nv[4];
            #pragma unroll
            for (int r = 0; r < 4; r++) {
                float v = 0.f;
                #pragma unroll
                for (int g = 0; g < 4; g++)
                    v += redf[((g * 64 + rhq) * 4 + r) * 4 + rc];
                float b = (i == 0) ? base0[r] : bbv;
                nv[r] = tanhfast(v + b);
            }
            a4[t] = make_float4(nv[0], nv[1], nv[2], nv[3]);
            __syncthreads();
        }
        // y = sigmoid(a @ Wy + by)
        {
            float4 acc[4];
            #pragma unroll
            for (int r = 0; r < 4; r++) acc[r] = make_float4(0.f, 0.f, 0.f, 0.f);
            gemv_part(Wy + h4, a4, kbase, acc);
            #pragma unroll
            for (int r = 0; r < 4; r++) red2[rbase + r] = acc[r];
            __syncthreads();
            #pragma unroll
            for (int r = 0; r < 4; r++) {
                float v = 0.f;
                #pragma unroll
                for (int g = 0; g < 4; g++)
                    v += red2f[((g * 64 + rhq) * 4 + r) * 4 + rc];
                out[((size_t)(b0 + r) * LL + i) * OO + t] = sigf(v + byv);
            }
        }
    }
}

// ---------------------------------------------------------------------------
extern "C" void kernel_launch(void* const* d_in, const int* in_sizes, int n_in,
                              void* d_out, int out_size)
{
    const float* x   = (const float*)d_in[0];
    const float* W1x = (const float*)d_in[1];
    const float* b1x = (const float*)d_in[2];
    const float* W1a = (const float*)d_in[3];
    const float* b1a = (const float*)d_in[4];
    const float* W2x = (const float*)d_in[5];
    const float* b2x = (const float*)d_in[6];
    const float* W2a = (const float*)d_in[7];
    const float* b2a = (const float*)d_in[8];
    const float* Wy  = (const float*)d_in[9];
    const float* by  = (const float*)d_in[10];
    float* out = (float*)d_out;

    (void)in_sizes; (void)n_in; (void)out_size;

    dim3 xgrid((BB * SS) / 64, HH / 64);
    xproj_kernel<<<xgrid, 256>>>(x, W1x, b1x, b1a);
    rnn_kernel<<<BB / 4, 256>>>(W1a, W2x, b2x, W2a, b2a, Wy, by, out);
}

// round 4
// speedup vs baseline: 1.9611x; 1.0300x over previous
#include <cuda_runtime.h>
#include <math.h>
#include <stdint.h>

#define BB 256
#define SS 512
#define II 256
#define HH 256
#define OO 256
#define LL 64

// Scratch: xproj[s][b][h] = x[b,s,:]@W1x + b1x + b1a
__device__ float g_xproj[(size_t)SS * BB * HH];

__device__ __forceinline__ float sigf(float x) { return 1.f / (1.f + expf(-x)); }
__device__ __forceinline__ float tanhfast(float x) {
    float e = expf(2.f * x);
    return 1.f - 2.f / (e + 1.f);
}

// ---------------------------------------------------------------------------
// PTX helpers (cluster DSMEM + mbarrier)
// ---------------------------------------------------------------------------
__device__ __forceinline__ uint32_t smem_u32(const void* p) {
    uint32_t r;
    asm("{ .reg .u64 t; cvta.to.shared.u64 t, %1; cvt.u32.u64 %0, t; }" : "=r"(r) : "l"(p));
    return r;
}
__device__ __forceinline__ uint32_t mapa_peer(uint32_t a, uint32_t peer) {
    uint32_t r;
    asm("mapa.shared::cluster.u32 %0, %1, %2;" : "=r"(r) : "r"(a), "r"(peer));
    return r;
}
__device__ __forceinline__ void mbar_init(uint32_t a, uint32_t c) {
    asm volatile("mbarrier.init.shared.b64 [%0], %1;" :: "r"(a), "r"(c) : "memory");
}
__device__ __forceinline__ void mbar_arrive_cluster(uint32_t a) {
    asm volatile("mbarrier.arrive.release.cluster.shared::cluster.b64 _, [%0];"
                 :: "r"(a) : "memory");
}
__device__ __forceinline__ void mbar_wait_par(uint32_t a, uint32_t par) {
    asm volatile(
        "{\n\t.reg .pred P;\n\t"
        "WL%=:\n\t"
        "mbarrier.try_wait.parity.acquire.cluster.shared::cta.b64 P, [%0], %1, 0x989680;\n\t"
        "@P bra WD%=;\n\t"
        "bra WL%=;\n\t"
        "WD%=:\n\t}"
        :: "r"(a), "r"(par) : "memory");
}
__device__ __forceinline__ void st_cluster_f4(uint32_t a, float4 v) {
    asm volatile("st.shared::cluster.v4.b32 [%0], {%1,%2,%3,%4};" :: "r"(a),
                 "r"(__float_as_uint(v.x)), "r"(__float_as_uint(v.y)),
                 "r"(__float_as_uint(v.z)), "r"(__float_as_uint(v.w)) : "memory");
}
__device__ __forceinline__ void cluster_sync_all() {
    asm volatile("barrier.cluster.arrive.aligned;" ::: "memory");
    asm volatile("barrier.cluster.wait.aligned;" ::: "memory");
}

// ---------------------------------------------------------------------------
// Kernel 1: xproj = x @ W1x + (b1x+b1a), tiled SGEMM (unchanged from R2).
// ---------------------------------------------------------------------------
__global__ __launch_bounds__(256) void xproj_kernel(
    const float* __restrict__ x, const float* __restrict__ W1x,
    const float* __restrict__ b1x, const float* __restrict__ b1a)
{
    __shared__ float As[2][16][64];
    __shared__ float Bs[2][16][64];

    const int t  = threadIdx.x;
    const int tx = t & 15;
    const int ty = t >> 4;
    const int m0 = blockIdx.x * 64;
    const int n0 = blockIdx.y * 64;
    const int s  = m0 >> 8;
    const int b0 = m0 & 255;

    const int ar = t >> 2;
    const int ak = t & 3;
    const int bk = t >> 4;
    const int bn = t & 15;

    const float* aptr = x + ((size_t)(b0 + ar) * SS + s) * II + ak * 4;
    const float* bptr = W1x + (size_t)bk * HH + n0 + bn * 4;

    float4 areg = *(const float4*)aptr;
    float4 breg = *(const float4*)bptr;
    As[0][ak * 4 + 0][ar] = areg.x;
    As[0][ak * 4 + 1][ar] = areg.y;
    As[0][ak * 4 + 2][ar] = areg.z;
    As[0][ak * 4 + 3][ar] = areg.w;
    *(float4*)&Bs[0][bk][bn * 4] = breg;
    __syncthreads();

    float4 acc[4];
    #pragma unroll
    for (int r = 0; r < 4; r++) acc[r] = make_float4(0.f, 0.f, 0.f, 0.f);

    #pragma unroll 1
    for (int step = 0; step < 16; step++) {
        const int p = step & 1;
        if (step < 15) {
            areg = *(const float4*)(aptr + (step + 1) * 16);
            breg = *(const float4*)(bptr + (size_t)(step + 1) * 16 * HH);
        }
        #pragma unroll
        for (int k = 0; k < 16; k++) {
            float4 av = *(const float4*)&As[p][k][ty * 4];
            float4 bv = *(const float4*)&Bs[p][k][tx * 4];
            acc[0].x = fmaf(av.x, bv.x, acc[0].x); acc[0].y = fmaf(av.x, bv.y, acc[0].y);
            acc[0].z = fmaf(av.x, bv.z, acc[0].z); acc[0].w = fmaf(av.x, bv.w, acc[0].w);
            acc[1].x = fmaf(av.y, bv.x, acc[1].x); acc[1].y = fmaf(av.y, bv.y, acc[1].y);
            acc[1].z = fmaf(av.y, bv.z, acc[1].z); acc[1].w = fmaf(av.y, bv.w, acc[1].w);
            acc[2].x = fmaf(av.z, bv.x, acc[2].x); acc[2].y = fmaf(av.z, bv.y, acc[2].y);
            acc[2].z = fmaf(av.z, bv.z, acc[2].z); acc[2].w = fmaf(av.z, bv.w, acc[2].w);
            acc[3].x = fmaf(av.w, bv.x, acc[3].x); acc[3].y = fmaf(av.w, bv.y, acc[3].y);
            acc[3].z = fmaf(av.w, bv.z, acc[3].z); acc[3].w = fmaf(av.w, bv.w, acc[3].w);
        }
        if (step < 15) {
            const int q2 = 1 - p;
            As[q2][ak * 4 + 0][ar] = areg.x;
            As[q2][ak * 4 + 1][ar] = areg.y;
            As[q2][ak * 4 + 2][ar] = areg.z;
            As[q2][ak * 4 + 3][ar] = areg.w;
            *(float4*)&Bs[q2][bk][bn * 4] = breg;
            __syncthreads();
        }
    }

    float4 bx = *(const float4*)&b1x[n0 + tx * 4];
    float4 ba = *(const float4*)&b1a[n0 + tx * 4];
    float4 bias = make_float4(bx.x + ba.x, bx.y + ba.y, bx.z + ba.z, bx.w + ba.w);
    #pragma unroll
    for (int r = 0; r < 4; r++) {
        float4 v = make_float4(acc[r].x + bias.x, acc[r].y + bias.y,
                               acc[r].z + bias.z, acc[r].w + bias.w);
        *(float4*)&g_xproj[(size_t)(m0 + ty * 4 + r) * HH + n0 + tx * 4] = v;
    }
}

// ---------------------------------------------------------------------------
// GEMV partial: thread (kq = warp, cq = lane). 32 k-iters: LDG.128 of 4 weight
// cols x LDS.128 broadcast of a[k] (4 batch rows) = 16 FMA per load pair.
// acc layout: acc[row*4 + ci].
// ---------------------------------------------------------------------------
__device__ __forceinline__ void gemv16(const float* __restrict__ Wp,
                                       const float4* __restrict__ a, float acc[16])
{
    #pragma unroll
    for (int j = 0; j < 16; j++) acc[j] = 0.f;
    #pragma unroll 8
    for (int k = 0; k < 32; k++) {
        float4 w  = *(const float4*)(Wp + (size_t)k * 256);
        float4 av = a[k];
        acc[0]  = fmaf(av.x, w.x, acc[0]);  acc[1]  = fmaf(av.x, w.y, acc[1]);
        acc[2]  = fmaf(av.x, w.z, acc[2]);  acc[3]  = fmaf(av.x, w.w, acc[3]);
        acc[4]  = fmaf(av.y, w.x, acc[4]);  acc[5]  = fmaf(av.y, w.y, acc[5]);
        acc[6]  = fmaf(av.y, w.z, acc[6]);  acc[7]  = fmaf(av.y, w.w, acc[7]);
        acc[8]  = fmaf(av.z, w.x, acc[8]);  acc[9]  = fmaf(av.z, w.y, acc[9]);
        acc[10] = fmaf(av.z, w.z, acc[10]); acc[11] = fmaf(av.z, w.w, acc[11]);
        acc[12] = fmaf(av.w, w.x, acc[12]); acc[13] = fmaf(av.w, w.y, acc[13]);
        acc[14] = fmaf(av.w, w.z, acc[14]); acc[15] = fmaf(av.w, w.w, acc[15]);
    }
}

#define RSTRIDE 1032   // padded row stride (floats) -> conflict-free reduction

// ---------------------------------------------------------------------------
// Kernel 2: cluster-2 N-split persistent RNN.
// Grid = 128 CTAs (64 clusters x 2). Cluster owns 4 batch rows; rank r owns
// hidden cols [128r,128r+128). W slices are L1-resident (128 KB).
// Encoder sync: mbarrier F (peer half arrived) / RD (peer buffer clear),
// count=32 elected-warp arrives. Decoder/glue: cluster.sync (cheap at 64 iters).
// ---------------------------------------------------------------------------
__global__ __launch_bounds__(256, 1) __cluster_dims__(2, 1, 1)
void rnn_kernel(const float* __restrict__ W1a,
                const float* __restrict__ W2x, const float* __restrict__ b2x,
                const float* __restrict__ W2a, const float* __restrict__ b2a,
                const float* __restrict__ Wy,  const float* __restrict__ by,
                float* __restrict__ out)
{
    __shared__ float4 a4s[2][256];                 // state, double-buffered
    __shared__ float4 y4s[256];                    // y0 staging
    __shared__ __align__(16) float red[4 * RSTRIDE];
    __shared__ __align__(8) unsigned long long mbars[4];  // F0,F1,RD0,RD1

    const int t  = threadIdx.x;
    const int kq = t >> 5;          // warp = k-octant
    const int cq = t & 31;          // lane = col-quad
    uint32_t rank;
    asm("mov.u32 %0, %%cluster_ctarank;" : "=r"(rank));
    const uint32_t peer = rank ^ 1;
    const int b0 = (blockIdx.x >> 1) * 4;
    const int c0 = (int)rank * 128;

    // this thread's 2 outputs: o = 2t, 2t+1  (o = cq_o*16 + row_o*4 + ci)
    const int o0    = 2 * t;
    const int cq_o  = o0 >> 4;
    const int row_o = (o0 >> 2) & 3;
    const int ci0   = o0 & 3;                // even
    const int coll  = cq_o * 4 + ci0;        // local col (0..127), even
    const int col   = c0 + coll;             // global col
    const int brow  = b0 + row_o;

    uint32_t mF[2], mRD[2], pF[2], pRD[2];
    mF[0]  = smem_u32(&mbars[0]); mF[1]  = smem_u32(&mbars[1]);
    mRD[0] = smem_u32(&mbars[2]); mRD[1] = smem_u32(&mbars[3]);
    pF[0]  = mapa_peer(mF[0], peer);  pF[1]  = mapa_peer(mF[1], peer);
    pRD[0] = mapa_peer(mRD[0], peer); pRD[1] = mapa_peer(mRD[1], peer);
    uint32_t pa4[2];
    pa4[0] = mapa_peer(smem_u32(&a4s[0][0]), peer);
    pa4[1] = mapa_peer(smem_u32(&a4s[1][0]), peer);
    uint32_t py4 = mapa_peer(smem_u32(&y4s[0]), peer);

    if (t == 0) {
        mbar_init(mF[0], 32);  mbar_init(mF[1], 32);
        mbar_init(mRD[0], 32); mbar_init(mRD[1], 32);
    }
    a4s[0][t] = make_float4(0.f, 0.f, 0.f, 0.f);
    __syncthreads();
    cluster_sync_all();                 // peer mbarriers initialized
    if (kq == 0) mbar_arrive_cluster(pF[0]);   // prime F[0] (initial zeros)
    if (kq == 1) mbar_arrive_cluster(pRD[1]);  // prime RD[1] (buf1 never read)

    int fpar[2]  = {0, 0};
    int rdpar[2] = {0, 0};

    const float* w1p  = W1a + (size_t)(kq * 32) * 256 + c0 + cq * 4;
    const float* wyp  = Wy  + (size_t)(kq * 32) * 256 + c0 + cq * 4;
    const float* w2ap = W2a + (size_t)(kq * 32) * 256 + c0 + cq * 4;
    const float* w2xp = W2x + (size_t)(kq * 32) * 256 + c0 + cq * 4;

    // ======================= encoder =======================
    for (int s = 0; s < SS; s++) {
        const int p = s & 1, q = p ^ 1;
        mbar_wait_par(mF[p], fpar[p]); fpar[p] ^= 1;   // buf p complete

        float2 xp = __ldcs((const float2*)(g_xproj + ((size_t)s * BB + brow) * HH + col));

        float acc[16];
        gemv16(w1p, &a4s[p][kq * 32], acc);
        #pragma unroll
        for (int r = 0; r < 4; r++)
            *(float4*)&red[r * RSTRIDE + kq * 128 + cq * 4] =
                make_float4(acc[r * 4], acc[r * 4 + 1], acc[r * 4 + 2], acc[r * 4 + 3]);
        __syncthreads();                                // sync1: reads of p done
        if (kq == 1) mbar_arrive_cluster(pRD[p]);       // tell peer: my buf p clear

        float v0 = 0.f, v1 = 0.f;
        #pragma unroll
        for (int g = 0; g < 8; g++) {
            float2 rv = *(const float2*)&red[row_o * RSTRIDE + g * 128 + coll];
            v0 += rv.x; v1 += rv.y;
        }
        v0 = tanhfast(v0 + xp.x);
        v1 = tanhfast(v1 + xp.y);
        ((float*)&a4s[q][col])[row_o]     = v0;
        ((float*)&a4s[q][col + 1])[row_o] = v1;
        __syncthreads();                                // sync2: local half of q done

        if (kq == 0) {                                  // copy warp: push my half
            mbar_wait_par(mRD[q], rdpar[q]); rdpar[q] ^= 1;   // peer buf q clear
            #pragma unroll
            for (int j = 0; j < 4; j++) {
                int idx = c0 + cq + 32 * j;
                st_cluster_f4(pa4[q] + (uint32_t)idx * 16u, a4s[q][idx]);
            }
            mbar_arrive_cluster(pF[q]);                 // peer's buf q now full
        }
    }

    // a_last is in a4s[0]; wait for peer half
    mbar_wait_par(mF[0], fpar[0]); fpar[0] ^= 1;

    // ======================= glue: y0, base0 =======================
    float byv0, byv1, bb0, bb1, base00, base01;
    {
        float2 byv = *(const float2*)&by[col];
        byv0 = byv.x; byv1 = byv.y;
        float2 b2xv = *(const float2*)&b2x[col];
        float2 b2av = *(const float2*)&b2a[col];
        bb0 = b2xv.x + b2av.x; bb1 = b2xv.y + b2av.y;

        float acc[16];
        gemv16(wyp, &a4s[0][kq * 32], acc);
        #pragma unroll
        for (int r = 0; r < 4; r++)
            *(float4*)&red[r * RSTRIDE + kq * 128 + cq * 4] =
                make_float4(acc[r * 4], acc[r * 4 + 1], acc[r * 4 + 2], acc[r * 4 + 3]);
        __syncthreads();
        float v0 = 0.f, v1 = 0.f;
        #pragma unroll
        for (int g = 0; g < 8; g++) {
            float2 rv = *(const float2*)&red[row_o * RSTRIDE + g * 128 + coll];
            v0 += rv.x; v1 += rv.y;
        }
        ((float*)&y4s[col])[row_o]     = sigf(v0 + byv0);
        ((float*)&y4s[col + 1])[row_o] = sigf(v1 + byv1);
        __syncthreads();
        if (kq == 0) {
            #pragma unroll
            for (int j = 0; j < 4; j++) {
                int idx = c0 + cq + 32 * j;
                st_cluster_f4(py4 + (uint32_t)idx * 16u, y4s[idx]);
            }
        }
        cluster_sync_all();                  // y0 complete in both CTAs

        gemv16(w2xp, &y4s[kq * 32], acc);
        #pragma unroll
        for (int r = 0; r < 4; r++)
            *(float4*)&red[r * RSTRIDE + kq * 128 + cq * 4] =
                make_float4(acc[r * 4], acc[r * 4 + 1], acc[r * 4 + 2], acc[r * 4 + 3]);
        __syncthreads();
        v0 = 0.f; v1 = 0.f;
        #pragma unroll
        for (int g = 0; g < 8; g++) {
            float2 rv = *(const float2*)&red[row_o * RSTRIDE + g * 128 + coll];
            v0 += rv.x; v1 += rv.y;
        }
        base00 = v0 + bb0; base01 = v1 + bb1;
        __syncthreads();                     // red reuse protection
    }

    // ======================= decoder =======================
    for (int i = 0; i < LL; i++) {
        const int p = i & 1, q = p ^ 1;
        float acc[16];

        // a = tanh(base + a @ W2a)
        gemv16(w2ap, &a4s[p][kq * 32], acc);
        #pragma unroll
        for (int r = 0; r < 4; r++)
            *(float4*)&red[r * RSTRIDE + kq * 128 + cq * 4] =
                make_float4(acc[r * 4], acc[r * 4 + 1], acc[r * 4 + 2], acc[r * 4 + 3]);
        __syncthreads();
        float v0 = 0.f, v1 = 0.f;
        #pragma unroll
        for (int g = 0; g < 8; g++) {
            float2 rv = *(const float2*)&red[row_o * RSTRIDE + g * 128 + coll];
            v0 += rv.x; v1 += rv.y;
        }
        float bs0 = (i == 0) ? base00 : bb0;
        float bs1 = (i == 0) ? base01 : bb1;
        ((float*)&a4s[q][col])[row_o]     = tanhfast(v0 + bs0);
        ((float*)&a4s[q][col + 1])[row_o] = tanhfast(v1 + bs1);
        __syncthreads();
        if (kq == 0) {
            #pragma unroll
            for (int j = 0; j < 4; j++) {
                int idx = c0 + cq + 32 * j;
                st_cluster_f4(pa4[q] + (uint32_t)idx * 16u, a4s[q][idx]);
            }
        }
        cluster_sync_all();                  // S1: new a complete everywhere

        // y = sigmoid(a @ Wy + by)
        gemv16(wyp, &a4s[q][kq * 32], acc);
        #pragma unroll
        for (int r = 0; r < 4; r++)
            *(float4*)&red[r * RSTRIDE + kq * 128 + cq * 4] =
                make_float4(acc[r * 4], acc[r * 4 + 1], acc[r * 4 + 2], acc[r * 4 + 3]);
        __syncthreads();
        v0 = 0.f; v1 = 0.f;
        #pragma unroll
        for (int g = 0; g < 8; g++) {
            float2 rv = *(const float2*)&red[row_o * RSTRIDE + g * 128 + coll];
            v0 += rv.x; v1 += rv.y;
        }
        float2 yo = make_float2(sigf(v0 + byv0), sigf(v1 + byv1));
        *(float2*)&out[((size_t)brow * LL + i) * OO + col] = yo;
        cluster_sync_all();                  // S2: protect buffers + red
    }
}

// ---------------------------------------------------------------------------
extern "C" void kernel_launch(void* const* d_in, const int* in_sizes, int n_in,
                              void* d_out, int out_size)
{
    const float* x   = (const float*)d_in[0];
    const float* W1x = (const float*)d_in[1];
    const float* b1x = (const float*)d_in[2];
    const float* W1a = (const float*)d_in[3];
    const float* b1a = (const float*)d_in[4];
    const float* W2x = (const float*)d_in[5];
    const float* b2x = (const float*)d_in[6];
    const float* W2a = (const float*)d_in[7];
    const float* b2a = (const float*)d_in[8];
    const float* Wy  = (const float*)d_in[9];
    const float* by  = (const float*)d_in[10];
    float* out = (float*)d_out;

    (void)in_sizes; (void)n_in; (void)out_size;

    dim3 xgrid((BB * SS) / 64, HH / 64);
    xproj_kernel<<<xgrid, 256>>>(x, W1x, b1x, b1a);
    rnn_kernel<<<BB / 2, 256>>>(W1a, W2x, b2x, W2a, b2a, Wy, by, out);
}

// round 5
// speedup vs baseline: 2.9145x; 1.4861x over previous
#include <cuda_runtime.h>
#include <math.h>
#include <stdint.h>

#define BB 256
#define SS 512
#define II 256
#define HH 256
#define OO 256
#define LL 64

__device__ float g_xproj[(size_t)SS * BB * HH];

__device__ __forceinline__ float sigf(float x) {
    return __fdividef(1.f, 1.f + __expf(-x));
}
__device__ __forceinline__ float tanhfast(float x) {
    float e = __expf(2.f * x);
    return 1.f - __fdividef(2.f, e + 1.f);
}

// ---------------------------------------------------------------------------
// PTX helpers
// ---------------------------------------------------------------------------
__device__ __forceinline__ uint32_t smem_u32(const void* p) {
    uint32_t r;
    asm("{ .reg .u64 t; cvta.to.shared.u64 t, %1; cvt.u32.u64 %0, t; }" : "=r"(r) : "l"(p));
    return r;
}
__device__ __forceinline__ uint32_t mapa_peer(uint32_t a, uint32_t peer) {
    uint32_t r;
    asm("mapa.shared::cluster.u32 %0, %1, %2;" : "=r"(r) : "r"(a), "r"(peer));
    return r;
}
__device__ __forceinline__ void mbar_init(uint32_t a, uint32_t c) {
    asm volatile("mbarrier.init.shared.b64 [%0], %1;" :: "r"(a), "r"(c) : "memory");
}
__device__ __forceinline__ void mbar_arrive_cluster(uint32_t a) {
    asm volatile("mbarrier.arrive.release.cluster.shared::cluster.b64 _, [%0];"
                 :: "r"(a) : "memory");
}
__device__ __forceinline__ void mbar_wait_par(uint32_t a, uint32_t par) {
    asm volatile(
        "{\n\t.reg .pred P;\n\t"
        "WL%=:\n\t"
        "mbarrier.try_wait.parity.acquire.cluster.shared::cta.b64 P, [%0], %1, 0x989680;\n\t"
        "@P bra WD%=;\n\t"
        "bra WL%=;\n\t"
        "WD%=:\n\t}"
        :: "r"(a), "r"(par) : "memory");
}
__device__ __forceinline__ void st_cluster_f4(uint32_t a, float4 v) {
    asm volatile("st.shared::cluster.v4.b32 [%0], {%1,%2,%3,%4};" :: "r"(a),
                 "r"(__float_as_uint(v.x)), "r"(__float_as_uint(v.y)),
                 "r"(__float_as_uint(v.z)), "r"(__float_as_uint(v.w)) : "memory");
}
__device__ __forceinline__ void cluster_sync_all() {
    asm volatile("barrier.cluster.arrive.aligned;" ::: "memory");
    asm volatile("barrier.cluster.wait.aligned;" ::: "memory");
}

// ---------------------------------------------------------------------------
// Kernel 1: xproj = x @ W1x + (b1x+b1a)  (tiled SGEMM, at fp32 FMA chip floor)
// ---------------------------------------------------------------------------
__global__ __launch_bounds__(256) void xproj_kernel(
    const float* __restrict__ x, const float* __restrict__ W1x,
    const float* __restrict__ b1x, const float* __restrict__ b1a)
{
    __shared__ float As[2][16][64];
    __shared__ float Bs[2][16][64];

    const int t  = threadIdx.x;
    const int tx = t & 15;
    const int ty = t >> 4;
    const int m0 = blockIdx.x * 64;
    const int n0 = blockIdx.y * 64;
    const int s  = m0 >> 8;
    const int b0 = m0 & 255;

    const int ar = t >> 2;
    const int ak = t & 3;
    const int bk = t >> 4;
    const int bn = t & 15;

    const float* aptr = x + ((size_t)(b0 + ar) * SS + s) * II + ak * 4;
    const float* bptr = W1x + (size_t)bk * HH + n0 + bn * 4;

    float4 areg = *(const float4*)aptr;
    float4 breg = *(const float4*)bptr;
    As[0][ak * 4 + 0][ar] = areg.x;
    As[0][ak * 4 + 1][ar] = areg.y;
    As[0][ak * 4 + 2][ar] = areg.z;
    As[0][ak * 4 + 3][ar] = areg.w;
    *(float4*)&Bs[0][bk][bn * 4] = breg;
    __syncthreads();

    float4 acc[4];
    #pragma unroll
    for (int r = 0; r < 4; r++) acc[r] = make_float4(0.f, 0.f, 0.f, 0.f);

    #pragma unroll 1
    for (int step = 0; step < 16; step++) {
        const int p = step & 1;
        if (step < 15) {
            areg = *(const float4*)(aptr + (step + 1) * 16);
            breg = *(const float4*)(bptr + (size_t)(step + 1) * 16 * HH);
        }
        #pragma unroll
        for (int k = 0; k < 16; k++) {
            float4 av = *(const float4*)&As[p][k][ty * 4];
            float4 bv = *(const float4*)&Bs[p][k][tx * 4];
            acc[0].x = fmaf(av.x, bv.x, acc[0].x); acc[0].y = fmaf(av.x, bv.y, acc[0].y);
            acc[0].z = fmaf(av.x, bv.z, acc[0].z); acc[0].w = fmaf(av.x, bv.w, acc[0].w);
            acc[1].x = fmaf(av.y, bv.x, acc[1].x); acc[1].y = fmaf(av.y, bv.y, acc[1].y);
            acc[1].z = fmaf(av.y, bv.z, acc[1].z); acc[1].w = fmaf(av.y, bv.w, acc[1].w);
            acc[2].x = fmaf(av.z, bv.x, acc[2].x); acc[2].y = fmaf(av.z, bv.y, acc[2].y);
            acc[2].z = fmaf(av.z, bv.z, acc[2].z); acc[2].w = fmaf(av.z, bv.w, acc[2].w);
            acc[3].x = fmaf(av.w, bv.x, acc[3].x); acc[3].y = fmaf(av.w, bv.y, acc[3].y);
            acc[3].z = fmaf(av.w, bv.z, acc[3].z); acc[3].w = fmaf(av.w, bv.w, acc[3].w);
        }
        if (step < 15) {
            const int q2 = 1 - p;
            As[q2][ak * 4 + 0][ar] = areg.x;
            As[q2][ak * 4 + 1][ar] = areg.y;
            As[q2][ak * 4 + 2][ar] = areg.z;
            As[q2][ak * 4 + 3][ar] = areg.w;
            *(float4*)&Bs[q2][bk][bn * 4] = breg;
            __syncthreads();
        }
    }

    float4 bx = *(const float4*)&b1x[n0 + tx * 4];
    float4 ba = *(const float4*)&b1a[n0 + tx * 4];
    float4 bias = make_float4(bx.x + ba.x, bx.y + ba.y, bx.z + ba.z, bx.w + ba.w);
    #pragma unroll
    for (int r = 0; r < 4; r++) {
        float4 v = make_float4(acc[r].x + bias.x, acc[r].y + bias.y,
                               acc[r].z + bias.z, acc[r].w + bias.w);
        *(float4*)&g_xproj[(size_t)(m0 + ty * 4 + r) * HH + n0 + tx * 4] = v;
    }
}

// ---------------------------------------------------------------------------
// GEMV partials. Thread (kq = warp 0..7, cq = lane). 32 k-iters, 16 FMA each.
// ---------------------------------------------------------------------------
__device__ __forceinline__ void gemv16_s(const float* __restrict__ Wp,   // smem, row stride 128
                                         const float4* __restrict__ a, float acc[16])
{
    #pragma unroll
    for (int j = 0; j < 16; j++) acc[j] = 0.f;
    #pragma unroll 8
    for (int k = 0; k < 32; k++) {
        float4 w  = *(const float4*)(Wp + k * 128);
        float4 av = a[k];
        acc[0]  = fmaf(av.x, w.x, acc[0]);  acc[1]  = fmaf(av.x, w.y, acc[1]);
        acc[2]  = fmaf(av.x, w.z, acc[2]);  acc[3]  = fmaf(av.x, w.w, acc[3]);
        acc[4]  = fmaf(av.y, w.x, acc[4]);  acc[5]  = fmaf(av.y, w.y, acc[5]);
        acc[6]  = fmaf(av.y, w.z, acc[6]);  acc[7]  = fmaf(av.y, w.w, acc[7]);
        acc[8]  = fmaf(av.z, w.x, acc[8]);  acc[9]  = fmaf(av.z, w.y, acc[9]);
        acc[10] = fmaf(av.z, w.z, acc[10]); acc[11] = fmaf(av.z, w.w, acc[11]);
        acc[12] = fmaf(av.w, w.x, acc[12]); acc[13] = fmaf(av.w, w.y, acc[13]);
        acc[14] = fmaf(av.w, w.z, acc[14]); acc[15] = fmaf(av.w, w.w, acc[15]);
    }
}
__device__ __forceinline__ void gemv16_g(const float* __restrict__ Wp,   // global, row stride 256
                                         const float4* __restrict__ a, float acc[16])
{
    #pragma unroll
    for (int j = 0; j < 16; j++) acc[j] = 0.f;
    #pragma unroll 16
    for (int k = 0; k < 32; k++) {
        float4 w  = *(const float4*)(Wp + (size_t)k * 256);
        float4 av = a[k];
        acc[0]  = fmaf(av.x, w.x, acc[0]);  acc[1]  = fmaf(av.x, w.y, acc[1]);
        acc[2]  = fmaf(av.x, w.z, acc[2]);  acc[3]  = fmaf(av.x, w.w, acc[3]);
        acc[4]  = fmaf(av.y, w.x, acc[4]);  acc[5]  = fmaf(av.y, w.y, acc[5]);
        acc[6]  = fmaf(av.y, w.z, acc[6]);  acc[7]  = fmaf(av.y, w.w, acc[7]);
        acc[8]  = fmaf(av.z, w.x, acc[8]);  acc[9]  = fmaf(av.z, w.y, acc[9]);
        acc[10] = fmaf(av.z, w.z, acc[10]); acc[11] = fmaf(av.z, w.w, acc[11]);
        acc[12] = fmaf(av.w, w.x, acc[12]); acc[13] = fmaf(av.w, w.y, acc[13]);
        acc[14] = fmaf(av.w, w.z, acc[14]); acc[15] = fmaf(av.w, w.w, acc[15]);
    }
}

#define RSTRIDE 1032

// SMEM layout (bytes):
//  ws     [32768 f] 131072   weight slice (W1a, later W2a), [k 0..255][128 local cols]
//  wy_lo  [16384 f]  65536   Wy rows k=0..127, local col slice (decoder)
//  a4s    [2][256] float4 8192
//  y4s    [256] float4    4096
//  red    [4*RSTRIDE f]  16512
//  mbars  [4] u64           32
#define SMEM_BYTES (131072 + 65536 + 8192 + 4096 + 16512 + 32)

// coalesced fill of a [nk x 128] smem slice from global [256 x 256] col block c0
__device__ __forceinline__ void fill_w(float* dst, const float* __restrict__ W,
                                       int c0, int t, int nk)
{
    const int lane = t & 31, w = t >> 5;
    for (int i = 0; i < nk / 8; i++) {
        int k = i * 8 + w;
        float4 v = *(const float4*)(W + (size_t)k * 256 + c0 + lane * 4);
        *(float4*)(dst + k * 128 + lane * 4) = v;
    }
}

// ---------------------------------------------------------------------------
// Kernel 2: cluster-2 N-split persistent RNN, SMEM-resident weights.
// ---------------------------------------------------------------------------
__global__ __launch_bounds__(256, 1) __cluster_dims__(2, 1, 1)
void rnn_kernel(const float* __restrict__ W1a,
                const float* __restrict__ W2x, const float* __restrict__ b2x,
                const float* __restrict__ W2a, const float* __restrict__ b2a,
                const float* __restrict__ Wy,  const float* __restrict__ by,
                float* __restrict__ out)
{
    extern __shared__ __align__(16) unsigned char dsm[];
    float*  ws    = (float*)dsm;
    float*  wy_lo = ws + 32768;
    float4* a4s   = (float4*)(wy_lo + 16384);   // [2][256]
    float4* y4s   = a4s + 512;
    float*  red   = (float*)(y4s + 256);
    unsigned long long* mbars = (unsigned long long*)(red + 4 * RSTRIDE);

    const int t  = threadIdx.x;
    const int kq = t >> 5;
    const int cq = t & 31;
    uint32_t rank;
    asm("mov.u32 %0, %%cluster_ctarank;" : "=r"(rank));
    const uint32_t peer = rank ^ 1;
    const int b0 = (blockIdx.x >> 1) * 4;
    const int c0 = (int)rank * 128;
    const bool is_peer = ((uint32_t)(kq >> 2) != rank);   // warp's k-half is peer's cols

    const int o0    = 2 * t;
    const int row_o = (o0 >> 2) & 3;
    const int coll  = (o0 >> 4) * 4 + (o0 & 3);
    const int col   = c0 + coll;
    const int brow  = b0 + row_o;

    uint32_t mF[2], mRD[2], pF[2], pRD[2];
    mF[0]  = smem_u32(&mbars[0]); mF[1]  = smem_u32(&mbars[1]);
    mRD[0] = smem_u32(&mbars[2]); mRD[1] = smem_u32(&mbars[3]);
    pF[0]  = mapa_peer(mF[0], peer);  pF[1]  = mapa_peer(mF[1], peer);
    pRD[0] = mapa_peer(mRD[0], peer); pRD[1] = mapa_peer(mRD[1], peer);
    uint32_t pa4[2];
    pa4[0] = mapa_peer(smem_u32(&a4s[0]), peer);
    pa4[1] = mapa_peer(smem_u32(&a4s[256]), peer);
    uint32_t py4 = mapa_peer(smem_u32(&y4s[0]), peer);

    if (t == 0) {
        mbar_init(mF[0], 32);  mbar_init(mF[1], 32);
        mbar_init(mRD[0], 32); mbar_init(mRD[1], 32);
    }
    a4s[t]       = make_float4(0.f, 0.f, 0.f, 0.f);
    fill_w(ws, W1a, c0, t, 256);                 // stage W1a slice
    __syncthreads();
    cluster_sync_all();
    if (kq == 0) mbar_arrive_cluster(pF[0]);
    if (kq == 1) mbar_arrive_cluster(pRD[1]);

    int fpar[2]  = {0, 0};
    int rdpar[2] = {0, 0};

    const float* wsp   = ws + kq * 32 * 128 + cq * 4;
    const float* wylop = wy_lo + kq * 32 * 128 + cq * 4;   // valid for kq<4

    // ======================= encoder =======================
    for (int s = 0; s < SS; s++) {
        const int p = s & 1, q = p ^ 1;
        float2 xp = __ldcs((const float2*)(g_xproj + ((size_t)s * BB + brow) * HH + col));

        if (is_peer) mbar_wait_par(mF[p], fpar[p]);
        fpar[p] ^= 1;

        float acc[16];
        gemv16_s(wsp, &a4s[p * 256 + kq * 32], acc);
        #pragma unroll
        for (int r = 0; r < 4; r++)
            *(float4*)&red[r * RSTRIDE + kq * 128 + cq * 4] =
                make_float4(acc[r * 4], acc[r * 4 + 1], acc[r * 4 + 2], acc[r * 4 + 3]);
        __syncthreads();                                // sync1
        if (kq == 1) mbar_arrive_cluster(pRD[p]);

        float v0 = 0.f, v1 = 0.f;
        #pragma unroll
        for (int g = 0; g < 8; g++) {
            float2 rv = *(const float2*)&red[row_o * RSTRIDE + g * 128 + coll];
            v0 += rv.x; v1 += rv.y;
        }
        ((float*)&a4s[q * 256 + col])[row_o]     = tanhfast(v0 + xp.x);
        ((float*)&a4s[q * 256 + col + 1])[row_o] = tanhfast(v1 + xp.y);
        __syncthreads();                                // sync2

        if (kq == 0) mbar_wait_par(mRD[q], rdpar[q]);
        rdpar[q] ^= 1;
        if (kq == 0) {
            #pragma unroll
            for (int j = 0; j < 4; j++) {
                int idx = c0 + cq + 32 * j;
                st_cluster_f4(pa4[q] + (uint32_t)idx * 16u, a4s[q * 256 + idx]);
            }
            mbar_arrive_cluster(pF[q]);
        }
    }

    // a_last in buf 0; peer half arrival
    if (is_peer) mbar_wait_par(mF[0], fpar[0]);
    fpar[0] ^= 1;

    // ======================= glue =======================
    float byv0, byv1, bb0, bb1, base00, base01;
    {
        float2 byv = *(const float2*)&by[col];
        byv0 = byv.x; byv1 = byv.y;
        float2 b2xv = *(const float2*)&b2x[col];
        float2 b2av = *(const float2*)&b2a[col];
        bb0 = b2xv.x + b2av.x; bb1 = b2xv.y + b2av.y;

        float acc[16];
        gemv16_g(Wy + (size_t)(kq * 32) * 256 + c0 + cq * 4, &a4s[kq * 32], acc);
        #pragma unroll
        for (int r = 0; r < 4; r++)
            *(float4*)&red[r * RSTRIDE + kq * 128 + cq * 4] =
                make_float4(acc[r * 4], acc[r * 4 + 1], acc[r * 4 + 2], acc[r * 4 + 3]);
        __syncthreads();
        float v0 = 0.f, v1 = 0.f;
        #pragma unroll
        for (int g = 0; g < 8; g++) {
            float2 rv = *(const float2*)&red[row_o * RSTRIDE + g * 128 + coll];
            v0 += rv.x; v1 += rv.y;
        }
        ((float*)&y4s[col])[row_o]     = sigf(v0 + byv0);
        ((float*)&y4s[col + 1])[row_o] = sigf(v1 + byv1);
        __syncthreads();
        if (kq == 0) {
            #pragma unroll
            for (int j = 0; j < 4; j++) {
                int idx = c0 + cq + 32 * j;
                st_cluster_f4(py4 + (uint32_t)idx * 16u, y4s[idx]);
            }
        }
        cluster_sync_all();     // y4s complete everywhere (one-time; L1 flush OK here)

        gemv16_g(W2x + (size_t)(kq * 32) * 256 + c0 + cq * 4, y4s + kq * 32, acc);
        #pragma unroll
        for (int r = 0; r < 4; r++)
            *(float4*)&red[r * RSTRIDE + kq * 128 + cq * 4] =
                make_float4(acc[r * 4], acc[r * 4 + 1], acc[r * 4 + 2], acc[r * 4 + 3]);
        __syncthreads();
        v0 = 0.f; v1 = 0.f;
        #pragma unroll
        for (int g = 0; g < 8; g++) {
            float2 rv = *(const float2*)&red[row_o * RSTRIDE + g * 128 + coll];
            v0 += rv.x; v1 += rv.y;
        }
        base00 = v0 + bb0; base01 = v1 + bb1;
        __syncthreads();
    }

    // restage weights for decoder: ws <- W2a slice, wy_lo <- Wy k<128 slice
    fill_w(ws, W2a, c0, t, 256);
    fill_w(wy_lo, Wy, c0, t, 128);
    __syncthreads();

    // ======================= decoder =======================
    for (int i = 0; i < LL; i++) {
        const int p = i & 1, q = p ^ 1;
        float acc[16];

        // a = tanh(base + a @ W2a)   (buf p peer-half already waited last iter/glue)
        gemv16_s(wsp, &a4s[p * 256 + kq * 32], acc);
        #pragma unroll
        for (int r = 0; r < 4; r++)
            *(float4*)&red[r * RSTRIDE + kq * 128 + cq * 4] =
                make_float4(acc[r * 4], acc[r * 4 + 1], acc[r * 4 + 2], acc[r * 4 + 3]);
        __syncthreads();                                // sync1
        if (kq == 1) mbar_arrive_cluster(pRD[p]);

        float v0 = 0.f, v1 = 0.f;
        #pragma unroll
        for (int g = 0; g < 8; g++) {
            float2 rv = *(const float2*)&red[row_o * RSTRIDE + g * 128 + coll];
            v0 += rv.x; v1 += rv.y;
        }
        float bs0 = (i == 0) ? base00 : bb0;
        float bs1 = (i == 0) ? base01 : bb1;
        ((float*)&a4s[q * 256 + col])[row_o]     = tanhfast(v0 + bs0);
        ((float*)&a4s[q * 256 + col + 1])[row_o] = tanhfast(v1 + bs1);
        __syncthreads();                                // sync2

        if (kq == 0) mbar_wait_par(mRD[q], rdpar[q]);
        rdpar[q] ^= 1;
        if (kq == 0) {
            #pragma unroll
            for (int j = 0; j < 4; j++) {
                int idx = c0 + cq + 32 * j;
                st_cluster_f4(pa4[q] + (uint32_t)idx * 16u, a4s[q * 256 + idx]);
            }
            mbar_arrive_cluster(pF[q]);
        }

        // y = sigmoid(a_new @ Wy + by): buf q, peer half via mF[q]
        if (is_peer) mbar_wait_par(mF[q], fpar[q]);
        fpar[q] ^= 1;

        if (kq < 4) gemv16_s(wylop, &a4s[q * 256 + kq * 32], acc);
        else        gemv16_g(Wy + (size_t)(kq * 32) * 256 + c0 + cq * 4,
                             &a4s[q * 256 + kq * 32], acc);
        #pragma unroll
        for (int r = 0; r < 4; r++)
            *(float4*)&red[r * RSTRIDE + kq * 128 + cq * 4] =
                make_float4(acc[r * 4], acc[r * 4 + 1], acc[r * 4 + 2], acc[r * 4 + 3]);
        __syncthreads();                                // sync3
        v0 = 0.f; v1 = 0.f;
        #pragma unroll
        for (int g = 0; g < 8; g++) {
            float2 rv = *(const float2*)&red[row_o * RSTRIDE + g * 128 + coll];
            v0 += rv.x; v1 += rv.y;
        }
        float2 yo = make_float2(sigf(v0 + byv0), sigf(v1 + byv1));
        *(float2*)&out[((size_t)brow * LL + i) * OO + col] = yo;
        __syncthreads();                                // sync4 (red reuse)
    }

    cluster_sync_all();     // no CTA exits while peer DSMEM ops may be in flight
}

// ---------------------------------------------------------------------------
extern "C" void kernel_launch(void* const* d_in, const int* in_sizes, int n_in,
                              void* d_out, int out_size)
{
    const float* x   = (const float*)d_in[0];
    const float* W1x = (const float*)d_in[1];
    const float* b1x = (const float*)d_in[2];
    const float* W1a = (const float*)d_in[3];
    const float* b1a = (const float*)d_in[4];
    const float* W2x = (const float*)d_in[5];
    const float* b2x = (const float*)d_in[6];
    const float* W2a = (const float*)d_in[7];
    const float* b2a = (const float*)d_in[8];
    const float* Wy  = (const float*)d_in[9];
    const float* by  = (const float*)d_in[10];
    float* out = (float*)d_out;

    (void)in_sizes; (void)n_in; (void)out_size;

    cudaFuncSetAttribute(rnn_kernel, cudaFuncAttributeMaxDynamicSharedMemorySize,
                         SMEM_BYTES);

    dim3 xgrid((BB * SS) / 64, HH / 64);
    xproj_kernel<<<xgrid, 256>>>(x, W1x, b1x, b1a);
    rnn_kernel<<<BB / 2, 256, SMEM_BYTES>>>(W1a, W2x, b2x, W2a, b2a, Wy, by, out);
}